// round 1
// baseline (speedup 1.0000x reference)
#include <cuda_runtime.h>
#include <cstddef>

#define NUM_NODES 100000
#define FEAT_DIM  256
#define BATCH     4096
#define F1N       25
#define F2N       10

// ---------------- static scratch (no runtime allocation allowed) ----------------
// PQ[m] row of 512: cols [0,256) = P = emb @ W1[:, :256].T ; cols [256,512) = Q = emb @ W1[:, 256:].T
__device__ float g_PQ[(size_t)NUM_NODES * 512];
__device__ float g_B1[256 * 512];   // [K=256][N=512] operand for PQ GEMM
__device__ float g_W2t[512 * 256];  // W2 transposed: [K=512][N=256]
__device__ float g_W3t[256 * 64];   // W3 transposed: [K=256][N=64]
__device__ float g_comb[BATCH * 512]; // [h0 | h1] per batch row
__device__ float g_E[BATCH * 256];    // embedding after W2 + relu

// ---------------- weight prep: build transposed operands ----------------
__global__ void prep_weights(const float* __restrict__ W1,
                             const float* __restrict__ W2,
                             const float* __restrict__ W3) {
    int idx = blockIdx.x * blockDim.x + threadIdx.x;  // launched with 131072 threads
    if (idx < 256 * 512) {  // g_B1: row k (0..255), col n (0..511)
        int k = idx >> 9, n = idx & 511;
        g_B1[idx] = (n < 256) ? W1[n * 512 + k] : W1[(n - 256) * 512 + 256 + k];
    }
    if (idx < 512 * 256) {  // g_W2t[k][n] = W2[n][k]
        int k = idx >> 8, n = idx & 255;
        g_W2t[idx] = W2[n * 512 + k];
    }
    if (idx < 256 * 64) {   // g_W3t[k][n] = W3[n][k]
        int k = idx >> 6, n = idx & 63;
        g_W3t[idx] = W3[n * 256 + k];
    }
}

// ---------------- generic fp32 tiled SGEMM: C[M,N] = A[M,K] * B[K,N] ----------------
// BM=128 BN=128 BK=16, 8x8 per thread, 256 threads. N and K must be multiples of 128/16
// (true for all uses here); M may have a tail (guarded).
template <bool RELU>
__global__ __launch_bounds__(256)
void sgemm128(const float* __restrict__ A, const float* __restrict__ B,
              float* __restrict__ C, int M, int N, int K) {
    const int BM = 128, BN = 128, BK = 16, TM = 8, TN = 8;
    __shared__ float As[BK][BM + 4];  // +4 pad kills store-phase bank conflicts
    __shared__ float Bs[BK][BN];

    int tid = threadIdx.x;
    int m0 = blockIdx.y * BM, n0 = blockIdx.x * BN;
    int tr = tid >> 4;       // 0..15
    int tc = tid & 15;       // 0..15

    float acc[TM][TN];
#pragma unroll
    for (int i = 0; i < TM; i++)
#pragma unroll
        for (int j = 0; j < TN; j++) acc[i][j] = 0.f;

    for (int k0 = 0; k0 < K; k0 += BK) {
        // A tile: 128x16 floats = 512 float4 / 256 threads = 2 each (transposed store)
#pragma unroll
        for (int it = 0; it < 2; it++) {
            int i = tid + it * 256;
            int row = i >> 2;
            int c4 = (i & 3) * 4;
            int gm = m0 + row;
            float4 v = make_float4(0.f, 0.f, 0.f, 0.f);
            if (gm < M)
                v = *reinterpret_cast<const float4*>(A + (size_t)gm * K + k0 + c4);
            As[c4 + 0][row] = v.x;
            As[c4 + 1][row] = v.y;
            As[c4 + 2][row] = v.z;
            As[c4 + 3][row] = v.w;
        }
        // B tile: 16x128 floats = 512 float4 / 256 threads = 2 each (direct store)
#pragma unroll
        for (int it = 0; it < 2; it++) {
            int i = tid + it * 256;
            int row = i >> 5;
            int c4 = (i & 31) * 4;
            *reinterpret_cast<float4*>(&Bs[row][c4]) =
                *reinterpret_cast<const float4*>(B + (size_t)(k0 + row) * N + n0 + c4);
        }
        __syncthreads();

#pragma unroll
        for (int k = 0; k < BK; k++) {
            float ra[TM], rb[TN];
#pragma unroll
            for (int i = 0; i < TM; i++) ra[i] = As[k][tr * TM + i];
#pragma unroll
            for (int j = 0; j < TN; j++) rb[j] = Bs[k][tc * TN + j];
#pragma unroll
            for (int i = 0; i < TM; i++)
#pragma unroll
                for (int j = 0; j < TN; j++) acc[i][j] = fmaf(ra[i], rb[j], acc[i][j]);
        }
        __syncthreads();
    }

#pragma unroll
    for (int i = 0; i < TM; i++) {
        int gm = m0 + tr * TM + i;
        if (gm >= M) break;
#pragma unroll
        for (int j = 0; j < TN; j += 4) {
            float4 v = make_float4(acc[i][j], acc[i][j + 1], acc[i][j + 2], acc[i][j + 3]);
            if (RELU) {
                v.x = fmaxf(v.x, 0.f); v.y = fmaxf(v.y, 0.f);
                v.z = fmaxf(v.z, 0.f); v.w = fmaxf(v.w, 0.f);
            }
            *reinterpret_cast<float4*>(C + (size_t)gm * N + n0 + tc * TN + j) = v;
        }
    }
}

// ---------------- fused gather / mean / relu: produces g_comb = [h0 | h1] ----------------
// One block per batch row b; thread d owns output dim d (0..255).
// h0[d] = relu(P[T0[b]][d] + (1/25) * sum_i Q[T1[b][i]][d])
// h1[d] = (1/25) * sum_i relu(P[T1[b][i]][d] + (1/10) * sum_j Q[T2[b*25+i][j]][d])
__global__ __launch_bounds__(256)
void gather_fuse(const int* __restrict__ T0, const int* __restrict__ T1,
                 const int* __restrict__ T2) {
    int b = blockIdx.x;
    int d = threadIdx.x;
    __shared__ int sT1[F1N];
    __shared__ int sT2[F1N * F2N];
    if (d < F1N) sT1[d] = T1[b * F1N + d];
    if (d < F1N * F2N) sT2[d] = T2[b * F1N * F2N + d];
    __syncthreads();

    const float* __restrict__ PQ = g_PQ;
    float qacc = 0.f, h1acc = 0.f;
#pragma unroll 1
    for (int i = 0; i < F1N; i++) {
        size_t m = (size_t)sT1[i] * 512;
        qacc += PQ[m + 256 + d];
        float s = PQ[m + d];
        float s2 = 0.f;
#pragma unroll
        for (int j = 0; j < F2N; j++) {
            s2 += PQ[(size_t)sT2[i * F2N + j] * 512 + 256 + d];
        }
        h1acc += fmaxf(fmaf(s2, 1.f / F2N, s), 0.f);
    }
    float p0 = PQ[(size_t)T0[b] * 512 + d];
    float h0 = fmaxf(fmaf(qacc, 1.f / F1N, p0), 0.f);
    g_comb[(size_t)b * 512 + d] = h0;
    g_comb[(size_t)b * 512 + 256 + d] = h1acc * (1.f / F1N);
}

// ---------------- final scores: out[b] = E[b] @ W3t  ([4096,256]x[256,64]) ----------------
__global__ __launch_bounds__(64)
void scores_k(float* __restrict__ out) {
    int b = blockIdx.x, t = threadIdx.x;  // 64 threads
    __shared__ float sE[256];
    for (int k = t; k < 256; k += 64) sE[k] = g_E[(size_t)b * 256 + k];
    __syncthreads();
    float s = 0.f;
#pragma unroll 8
    for (int k = 0; k < 256; k++) s = fmaf(sE[k], g_W3t[k * 64 + t], s);
    out[(size_t)b * 64 + t] = s;
}

// ---------------- launch ----------------
extern "C" void kernel_launch(void* const* d_in, const int* in_sizes, int n_in,
                              void* d_out, int out_size) {
    const int*   T0  = (const int*)d_in[0];
    const int*   T1  = (const int*)d_in[1];
    const int*   T2  = (const int*)d_in[2];
    const float* emb = (const float*)d_in[3];
    const float* W1  = (const float*)d_in[4];
    const float* W2  = (const float*)d_in[5];
    const float* W3  = (const float*)d_in[6];
    float* out = (float*)d_out;
    (void)in_sizes; (void)n_in; (void)out_size;

    float *PQ, *B1, *W2t, *comb, *E;
    cudaGetSymbolAddress((void**)&PQ,   g_PQ);
    cudaGetSymbolAddress((void**)&B1,   g_B1);
    cudaGetSymbolAddress((void**)&W2t,  g_W2t);
    cudaGetSymbolAddress((void**)&comb, g_comb);
    cudaGetSymbolAddress((void**)&E,    g_E);

    // 1) weight transposes
    prep_weights<<<512, 256>>>(W1, W2, W3);

    // 2) dense node-table GEMM: PQ[100000,512] = emb[100000,256] @ B1[256,512]
    {
        dim3 grid(512 / 128, (NUM_NODES + 127) / 128);
        sgemm128<false><<<grid, 256>>>(emb, B1, PQ, NUM_NODES, 512, 256);
    }

    // 3) fused gathers/means/relu -> g_comb [4096, 512]
    gather_fuse<<<BATCH, 256>>>(T0, T1, T2);

    // 4) embedding = relu(comb @ W2t): [4096,512]x[512,256]
    {
        dim3 grid(256 / 128, BATCH / 128);
        sgemm128<true><<<grid, 256>>>(comb, W2t, E, BATCH, 256, 512);
    }

    // 5) scores = E @ W3t : [4096,256]x[256,64]
    scores_k<<<BATCH, 64>>>(out);
}

// round 2
// speedup vs baseline: 2.0084x; 2.0084x over previous
#include <cuda_runtime.h>
#include <cstdint>
#include <cstddef>

#define NUM_NODES 100000
#define FEAT_DIM  256
#define BATCH     4096
#define F1N       25
#define F2N       10

// ---------------- static scratch (no runtime allocation allowed) ----------------
__device__ float g_PQ[(size_t)NUM_NODES * 512];
__device__ float g_B1[256 * 512];    // [K=256][N=512] operand for PQ GEMM
__device__ float g_W2t[512 * 256];   // W2 transposed: [K=512][N=256]
__device__ float g_W3t[256 * 64];    // W3 transposed: [K=256][N=64]
__device__ float g_comb[BATCH * 512];
__device__ float g_E[BATCH * 256];

// ---------------- weight prep ----------------
__global__ void prep_weights(const float* __restrict__ W1,
                             const float* __restrict__ W2,
                             const float* __restrict__ W3) {
    int idx = blockIdx.x * blockDim.x + threadIdx.x;
    if (idx < 256 * 512) {
        int k = idx >> 9, n = idx & 511;
        g_B1[idx] = (n < 256) ? W1[n * 512 + k] : W1[(n - 256) * 512 + 256 + k];
    }
    if (idx < 512 * 256) {
        int k = idx >> 8, n = idx & 255;
        g_W2t[idx] = W2[n * 512 + k];
    }
    if (idx < 256 * 64) {
        int k = idx >> 6, n = idx & 63;
        g_W3t[idx] = W3[n * 256 + k];
    }
}

// ---------------- TF32 tensor-core GEMM ----------------
// C[M,N] = A[M,K] * B[K,N]   (row-major A, B, C), optional fused ReLU.
// BM=128 BN=128 BK=16, 256 threads = 8 warps in 4(M) x 2(N), warp tile 32x64.
// Requires N % 128 == 0, K % 16 == 0. M may have a tail (guarded).

__device__ __forceinline__ uint32_t f2tf32(float f) {
    uint32_t r;
    asm("cvt.rna.tf32.f32 %0, %1;" : "=r"(r) : "f"(f));
    return r;
}

#define APITCH 20   // smem pitch for As rows (conflict-free fragment loads)
#define BPITCH 136  // smem pitch for Bs rows

template <bool RELU>
__global__ __launch_bounds__(256)
void gemm_tf32(const float* __restrict__ A, const float* __restrict__ B,
               float* __restrict__ C, int M, int N, int K) {
    __shared__ uint32_t As[128 * APITCH];   // [m][k] as tf32 bits
    __shared__ uint32_t Bs[16 * BPITCH];    // [k][n] as tf32 bits

    const int tid  = threadIdx.x;
    const int lane = tid & 31;
    const int wid  = tid >> 5;
    const int warpM = wid & 3;         // 0..3 -> 32-row slab
    const int warpN = wid >> 2;        // 0..1 -> 64-col slab
    const int gid = lane >> 2;         // 0..7
    const int lg  = lane & 3;          // 0..3

    const int m0 = blockIdx.y * 128;
    const int n0 = blockIdx.x * 128;

    float acc[2][8][4];
#pragma unroll
    for (int mt = 0; mt < 2; mt++)
#pragma unroll
        for (int nt = 0; nt < 8; nt++)
#pragma unroll
            for (int c = 0; c < 4; c++) acc[mt][nt][c] = 0.f;

    // per-thread tile-load coordinates (2 float4 each for A and B)
    const int arow0 = tid >> 2;            // 0..63   (it adds +64)
    const int akc   = (tid & 3) * 4;       // 0,4,8,12
    const int brow0 = tid >> 5;            // 0..7    (it adds +8)
    const int bnc   = (tid & 31) * 4;      // 0..124 step 4

    float4 pa[2], pb[2];
    // prefetch tile 0
#pragma unroll
    for (int it = 0; it < 2; it++) {
        int gm = m0 + arow0 + it * 64;
        pa[it] = (gm < M) ? *reinterpret_cast<const float4*>(A + (size_t)gm * K + akc)
                          : make_float4(0.f, 0.f, 0.f, 0.f);
        pb[it] = *reinterpret_cast<const float4*>(B + (size_t)(brow0 + it * 8) * N + n0 + bnc);
    }

    for (int k0 = 0; k0 < K; k0 += 16) {
        // store prefetched tile (convert to tf32 bits)
#pragma unroll
        for (int it = 0; it < 2; it++) {
            uint32_t* pA = &As[(arow0 + it * 64) * APITCH + akc];
            pA[0] = f2tf32(pa[it].x); pA[1] = f2tf32(pa[it].y);
            pA[2] = f2tf32(pa[it].z); pA[3] = f2tf32(pa[it].w);
            uint32_t* pB = &Bs[(brow0 + it * 8) * BPITCH + bnc];
            pB[0] = f2tf32(pb[it].x); pB[1] = f2tf32(pb[it].y);
            pB[2] = f2tf32(pb[it].z); pB[3] = f2tf32(pb[it].w);
        }
        __syncthreads();

        // prefetch next tile
        if (k0 + 16 < K) {
#pragma unroll
            for (int it = 0; it < 2; it++) {
                int gm = m0 + arow0 + it * 64;
                pa[it] = (gm < M) ? *reinterpret_cast<const float4*>(
                                        A + (size_t)gm * K + k0 + 16 + akc)
                                  : make_float4(0.f, 0.f, 0.f, 0.f);
                pb[it] = *reinterpret_cast<const float4*>(
                    B + (size_t)(k0 + 16 + brow0 + it * 8) * N + n0 + bnc);
            }
        }

        // compute 2 k-steps of 8
#pragma unroll
        for (int kk = 0; kk < 2; kk++) {
            uint32_t afr[2][4];
#pragma unroll
            for (int mt = 0; mt < 2; mt++) {
                int mb = (warpM * 32 + mt * 16 + gid) * APITCH + kk * 8 + lg;
                afr[mt][0] = As[mb];
                afr[mt][1] = As[mb + 8 * APITCH];
                afr[mt][2] = As[mb + 4];
                afr[mt][3] = As[mb + 8 * APITCH + 4];
            }
#pragma unroll
            for (int nt = 0; nt < 8; nt++) {
                int nb = (kk * 8 + lg) * BPITCH + warpN * 64 + nt * 8 + gid;
                uint32_t b0 = Bs[nb];
                uint32_t b1 = Bs[nb + 4 * BPITCH];
#pragma unroll
                for (int mt = 0; mt < 2; mt++) {
                    asm volatile(
                        "mma.sync.aligned.m16n8k8.row.col.f32.tf32.tf32.f32 "
                        "{%0,%1,%2,%3}, {%4,%5,%6,%7}, {%8,%9}, {%0,%1,%2,%3};\n"
                        : "+f"(acc[mt][nt][0]), "+f"(acc[mt][nt][1]),
                          "+f"(acc[mt][nt][2]), "+f"(acc[mt][nt][3])
                        : "r"(afr[mt][0]), "r"(afr[mt][1]),
                          "r"(afr[mt][2]), "r"(afr[mt][3]),
                          "r"(b0), "r"(b1));
                }
            }
        }
        __syncthreads();
    }

    // epilogue
#pragma unroll
    for (int mt = 0; mt < 2; mt++) {
        int r0 = m0 + warpM * 32 + mt * 16 + gid;
#pragma unroll
        for (int half = 0; half < 2; half++) {
            int gm = r0 + half * 8;
            if (gm >= M) continue;
#pragma unroll
            for (int nt = 0; nt < 8; nt++) {
                float x = acc[mt][nt][half * 2 + 0];
                float y = acc[mt][nt][half * 2 + 1];
                if (RELU) { x = fmaxf(x, 0.f); y = fmaxf(y, 0.f); }
                int col = n0 + warpN * 64 + nt * 8 + lg * 2;
                *reinterpret_cast<float2*>(C + (size_t)gm * N + col) = make_float2(x, y);
            }
        }
    }
}

// ---------------- fused gather / mean / relu ----------------
__global__ __launch_bounds__(256)
void gather_fuse(const int* __restrict__ T0, const int* __restrict__ T1,
                 const int* __restrict__ T2) {
    int b = blockIdx.x;
    int d = threadIdx.x;
    __shared__ int sT1[F1N];
    __shared__ int sT2[F1N * F2N];
    if (d < F1N) sT1[d] = T1[b * F1N + d];
    if (d < F1N * F2N) sT2[d] = T2[b * F1N * F2N + d];
    __syncthreads();

    const float* __restrict__ PQ = g_PQ;
    float qacc = 0.f, h1acc = 0.f;
#pragma unroll 1
    for (int i = 0; i < F1N; i++) {
        size_t m = (size_t)sT1[i] * 512;
        qacc += PQ[m + 256 + d];
        float s = PQ[m + d];
        float s2 = 0.f;
#pragma unroll
        for (int j = 0; j < F2N; j++) {
            s2 += PQ[(size_t)sT2[i * F2N + j] * 512 + 256 + d];
        }
        h1acc += fmaxf(fmaf(s2, 1.f / F2N, s), 0.f);
    }
    float p0 = PQ[(size_t)T0[b] * 512 + d];
    float h0 = fmaxf(fmaf(qacc, 1.f / F1N, p0), 0.f);
    g_comb[(size_t)b * 512 + d] = h0;
    g_comb[(size_t)b * 512 + 256 + d] = h1acc * (1.f / F1N);
}

// ---------------- final scores (kept exact fp32) ----------------
__global__ __launch_bounds__(64)
void scores_k(float* __restrict__ out) {
    int b = blockIdx.x, t = threadIdx.x;
    __shared__ float sE[256];
    for (int k = t; k < 256; k += 64) sE[k] = g_E[(size_t)b * 256 + k];
    __syncthreads();
    float s = 0.f;
#pragma unroll 8
    for (int k = 0; k < 256; k++) s = fmaf(sE[k], g_W3t[k * 64 + t], s);
    out[(size_t)b * 64 + t] = s;
}

// ---------------- launch ----------------
extern "C" void kernel_launch(void* const* d_in, const int* in_sizes, int n_in,
                              void* d_out, int out_size) {
    const int*   T0  = (const int*)d_in[0];
    const int*   T1  = (const int*)d_in[1];
    const int*   T2  = (const int*)d_in[2];
    const float* emb = (const float*)d_in[3];
    const float* W1  = (const float*)d_in[4];
    const float* W2  = (const float*)d_in[5];
    const float* W3  = (const float*)d_in[6];
    float* out = (float*)d_out;
    (void)in_sizes; (void)n_in; (void)out_size;

    float *PQ, *B1, *W2t, *comb, *E;
    cudaGetSymbolAddress((void**)&PQ,   g_PQ);
    cudaGetSymbolAddress((void**)&B1,   g_B1);
    cudaGetSymbolAddress((void**)&W2t,  g_W2t);
    cudaGetSymbolAddress((void**)&comb, g_comb);
    cudaGetSymbolAddress((void**)&E,    g_E);

    // 1) weight transposes
    prep_weights<<<512, 256>>>(W1, W2, W3);

    // 2) dense node-table GEMM (tf32 tensor cores):
    //    PQ[100000,512] = emb[100000,256] @ B1[256,512]
    {
        dim3 grid(512 / 128, (NUM_NODES + 127) / 128);
        gemm_tf32<false><<<grid, 256>>>(emb, B1, PQ, NUM_NODES, 512, 256);
    }

    // 3) fused gathers/means/relu -> g_comb [4096, 512]
    gather_fuse<<<BATCH, 256>>>(T0, T1, T2);

    // 4) embedding = relu(comb @ W2t): [4096,512]x[512,256]  (tf32)
    {
        dim3 grid(256 / 128, BATCH / 128);
        gemm_tf32<true><<<grid, 256>>>(comb, W2t, E, BATCH, 256, 512);
    }

    // 5) scores = E @ W3t : [4096,256]x[256,64]  (fp32 exact)
    scores_k<<<BATCH, 64>>>(out);
}

// round 3
// speedup vs baseline: 2.2632x; 1.1269x over previous
#include <cuda_runtime.h>
#include <cuda_fp16.h>
#include <cstdint>
#include <cstddef>

#define NUM_NODES 100000
#define FEAT_DIM  256
#define BATCH     4096
#define F1N       25
#define F2N       10

// ---------------- static scratch ----------------
__device__ __half g_PQh[(size_t)NUM_NODES * 512];  // fp16 [P | Q] per node
__device__ float g_B1[256 * 512];    // [K=256][N=512] operand for PQ GEMM
__device__ float g_W2t[512 * 256];   // W2 transposed: [K=512][N=256]
__device__ float g_W3t[256 * 64];    // W3 transposed: [K=256][N=64]
__device__ float g_comb[BATCH * 512];
__device__ float g_E[BATCH * 256];

// ---------------- weight prep ----------------
__global__ void prep_weights(const float* __restrict__ W1,
                             const float* __restrict__ W2,
                             const float* __restrict__ W3) {
    int idx = blockIdx.x * blockDim.x + threadIdx.x;
    if (idx < 256 * 512) {
        int k = idx >> 9, n = idx & 511;
        g_B1[idx] = (n < 256) ? W1[n * 512 + k] : W1[(n - 256) * 512 + 256 + k];
    }
    if (idx < 512 * 256) {
        int k = idx >> 8, n = idx & 255;
        g_W2t[idx] = W2[n * 512 + k];
    }
    if (idx < 256 * 64) {
        int k = idx >> 6, n = idx & 63;
        g_W3t[idx] = W3[n * 256 + k];
    }
}

// ---------------- TF32 tensor-core GEMM ----------------
// C[M,N] = A[M,K] * B[K,N], row-major, optional fused ReLU, fp32 or fp16 out.
// 256 threads = 8 warps arranged 4(M) x 2(N). Warp tile = (MT*16) x 64.
// BM = MT*64 (MT=2 -> 128, MT=1 -> 64). BN = 128. BK = 16.
// Requires N % 128 == 0, K % 16 == 0; M tail guarded.

__device__ __forceinline__ uint32_t f2tf32(float f) {
    uint32_t r;
    asm("cvt.rna.tf32.f32 %0, %1;" : "=r"(r) : "f"(f));
    return r;
}

__device__ __forceinline__ void store2(float* C, size_t off, float x, float y) {
    *reinterpret_cast<float2*>(C + off) = make_float2(x, y);
}
__device__ __forceinline__ void store2(__half* C, size_t off, float x, float y) {
    *reinterpret_cast<__half2*>(C + off) = __floats2half2_rn(x, y);
}

#define APITCH 20   // smem pitch for As rows (conflict-free fragment loads)
#define BPITCH 136  // smem pitch for Bs rows

template <bool RELU, int MT, typename OutT>
__global__ __launch_bounds__(256, 2)
void gemm_tf32(const float* __restrict__ A, const float* __restrict__ B,
               OutT* __restrict__ C, int M, int N, int K) {
    const int BM = MT * 64;
    __shared__ uint32_t As[BM * APITCH];    // [m][k] tf32 bits
    __shared__ uint32_t Bs[16 * BPITCH];    // [k][n] tf32 bits

    const int tid  = threadIdx.x;
    const int lane = tid & 31;
    const int wid  = tid >> 5;
    const int warpM = wid & 3;         // 4 M-slabs
    const int warpN = wid >> 2;        // 2 N-slabs of 64
    const int gid = lane >> 2;         // 0..7
    const int lg  = lane & 3;          // 0..3

    const int m0 = blockIdx.y * BM;
    const int n0 = blockIdx.x * 128;

    float acc[MT][8][4];
#pragma unroll
    for (int mt = 0; mt < MT; mt++)
#pragma unroll
        for (int nt = 0; nt < 8; nt++)
#pragma unroll
            for (int c = 0; c < 4; c++) acc[mt][nt][c] = 0.f;

    // tile-load coords: A = BM x 16 -> BM*4 float4 / 256 thr = MT each
    const int arow0 = tid >> 2;            // 0..63 (+64 per it)
    const int akc   = (tid & 3) * 4;       // 0,4,8,12
    const int brow0 = tid >> 5;            // 0..7  (+8 per it)
    const int bnc   = (tid & 31) * 4;      // 0..124 step 4

    float4 pa[MT], pb[2];
#pragma unroll
    for (int it = 0; it < MT; it++) {
        int gm = m0 + arow0 + it * 64;
        pa[it] = (gm < M) ? *reinterpret_cast<const float4*>(A + (size_t)gm * K + akc)
                          : make_float4(0.f, 0.f, 0.f, 0.f);
    }
#pragma unroll
    for (int it = 0; it < 2; it++)
        pb[it] = *reinterpret_cast<const float4*>(B + (size_t)(brow0 + it * 8) * N + n0 + bnc);

    for (int k0 = 0; k0 < K; k0 += 16) {
#pragma unroll
        for (int it = 0; it < MT; it++) {
            uint32_t* pA = &As[(arow0 + it * 64) * APITCH + akc];
            pA[0] = f2tf32(pa[it].x); pA[1] = f2tf32(pa[it].y);
            pA[2] = f2tf32(pa[it].z); pA[3] = f2tf32(pa[it].w);
        }
#pragma unroll
        for (int it = 0; it < 2; it++) {
            uint32_t* pB = &Bs[(brow0 + it * 8) * BPITCH + bnc];
            pB[0] = f2tf32(pb[it].x); pB[1] = f2tf32(pb[it].y);
            pB[2] = f2tf32(pb[it].z); pB[3] = f2tf32(pb[it].w);
        }
        __syncthreads();

        if (k0 + 16 < K) {
#pragma unroll
            for (int it = 0; it < MT; it++) {
                int gm = m0 + arow0 + it * 64;
                pa[it] = (gm < M) ? *reinterpret_cast<const float4*>(
                                        A + (size_t)gm * K + k0 + 16 + akc)
                                  : make_float4(0.f, 0.f, 0.f, 0.f);
            }
#pragma unroll
            for (int it = 0; it < 2; it++)
                pb[it] = *reinterpret_cast<const float4*>(
                    B + (size_t)(k0 + 16 + brow0 + it * 8) * N + n0 + bnc);
        }

#pragma unroll
        for (int kk = 0; kk < 2; kk++) {
            uint32_t afr[MT][4];
#pragma unroll
            for (int mt = 0; mt < MT; mt++) {
                int mb = (warpM * 16 * MT + mt * 16 + gid) * APITCH + kk * 8 + lg;
                afr[mt][0] = As[mb];
                afr[mt][1] = As[mb + 8 * APITCH];
                afr[mt][2] = As[mb + 4];
                afr[mt][3] = As[mb + 8 * APITCH + 4];
            }
#pragma unroll
            for (int nt = 0; nt < 8; nt++) {
                int nb = (kk * 8 + lg) * BPITCH + warpN * 64 + nt * 8 + gid;
                uint32_t b0 = Bs[nb];
                uint32_t b1 = Bs[nb + 4 * BPITCH];
#pragma unroll
                for (int mt = 0; mt < MT; mt++) {
                    asm volatile(
                        "mma.sync.aligned.m16n8k8.row.col.f32.tf32.tf32.f32 "
                        "{%0,%1,%2,%3}, {%4,%5,%6,%7}, {%8,%9}, {%0,%1,%2,%3};\n"
                        : "+f"(acc[mt][nt][0]), "+f"(acc[mt][nt][1]),
                          "+f"(acc[mt][nt][2]), "+f"(acc[mt][nt][3])
                        : "r"(afr[mt][0]), "r"(afr[mt][1]),
                          "r"(afr[mt][2]), "r"(afr[mt][3]),
                          "r"(b0), "r"(b1));
                }
            }
        }
        __syncthreads();
    }

#pragma unroll
    for (int mt = 0; mt < MT; mt++) {
        int r0 = m0 + warpM * 16 * MT + mt * 16 + gid;
#pragma unroll
        for (int half = 0; half < 2; half++) {
            int gm = r0 + half * 8;
            if (gm >= M) continue;
#pragma unroll
            for (int nt = 0; nt < 8; nt++) {
                float x = acc[mt][nt][half * 2 + 0];
                float y = acc[mt][nt][half * 2 + 1];
                if (RELU) { x = fmaxf(x, 0.f); y = fmaxf(y, 0.f); }
                int col = n0 + warpN * 64 + nt * 8 + lg * 2;
                store2(C, (size_t)gm * N + col, x, y);
            }
        }
    }
}

// ---------------- fused gather / mean / relu (fp16 PQ, half2 lanes) ----------------
// 128 threads; thread d2 owns dims {2*d2, 2*d2+1}. PQ2 row pitch = 256 half2.
__global__ __launch_bounds__(128)
void gather_fuse(const int* __restrict__ T0, const int* __restrict__ T1,
                 const int* __restrict__ T2) {
    int b = blockIdx.x;
    int d2 = threadIdx.x;
    __shared__ int sT1[F1N];
    __shared__ int sT2[F1N * F2N];
    if (d2 < F1N) sT1[d2] = T1[b * F1N + d2];
    for (int i = d2; i < F1N * F2N; i += 128) sT2[i] = T2[b * F1N * F2N + i];
    __syncthreads();

    const __half2* __restrict__ PQ2 = reinterpret_cast<const __half2*>(g_PQh);
    float qx = 0.f, qy = 0.f, hx = 0.f, hy = 0.f;
#pragma unroll 1
    for (int i = 0; i < F1N; i++) {
        size_t m = (size_t)sT1[i] * 256;
        float2 q = __half22float2(PQ2[m + 128 + d2]);
        qx += q.x; qy += q.y;
        float2 p = __half22float2(PQ2[m + d2]);
        float sx = 0.f, sy = 0.f;
#pragma unroll
        for (int j = 0; j < F2N; j++) {
            float2 v = __half22float2(PQ2[(size_t)sT2[i * F2N + j] * 256 + 128 + d2]);
            sx += v.x; sy += v.y;
        }
        hx += fmaxf(fmaf(sx, 1.f / F2N, p.x), 0.f);
        hy += fmaxf(fmaf(sy, 1.f / F2N, p.y), 0.f);
    }
    float2 p0 = __half22float2(PQ2[(size_t)T0[b] * 256 + d2]);
    float h0x = fmaxf(fmaf(qx, 1.f / F1N, p0.x), 0.f);
    float h0y = fmaxf(fmaf(qy, 1.f / F1N, p0.y), 0.f);
    *reinterpret_cast<float2*>(&g_comb[(size_t)b * 512 + 2 * d2]) = make_float2(h0x, h0y);
    *reinterpret_cast<float2*>(&g_comb[(size_t)b * 512 + 256 + 2 * d2]) =
        make_float2(hx * (1.f / F1N), hy * (1.f / F1N));
}

// ---------------- scores: 32 batch rows per block, E staged in smem ----------------
__global__ __launch_bounds__(256)
void scores_k(float* __restrict__ out) {
    int b0 = blockIdx.x * 32;
    __shared__ float sE[32 * 257];  // padded: bank(r*257+k) = (r+k)%32

    int tid = threadIdx.x;
#pragma unroll
    for (int it = 0; it < 8; it++) {
        int i = tid + it * 256;              // 0..2047, each covers 4 floats
        int r = i >> 6, k4 = (i & 63) * 4;
        float4 v = *reinterpret_cast<const float4*>(&g_E[(size_t)(b0 + r) * 256 + k4]);
        float* p = &sE[r * 257 + k4];
        p[0] = v.x; p[1] = v.y; p[2] = v.z; p[3] = v.w;
    }
    __syncthreads();

    int col = tid & 63, rg = tid >> 6;       // 4 row-groups of 8
    float a[8];
#pragma unroll
    for (int i = 0; i < 8; i++) a[i] = 0.f;
#pragma unroll 4
    for (int k = 0; k < 256; k++) {
        float w = g_W3t[k * 64 + col];
        const float* pe = &sE[(rg * 8) * 257 + k];
#pragma unroll
        for (int i = 0; i < 8; i++) a[i] = fmaf(pe[i * 257], w, a[i]);
    }
#pragma unroll
    for (int i = 0; i < 8; i++)
        out[(size_t)(b0 + rg * 8 + i) * 64 + col] = a[i];
}

// ---------------- launch ----------------
extern "C" void kernel_launch(void* const* d_in, const int* in_sizes, int n_in,
                              void* d_out, int out_size) {
    const int*   T0  = (const int*)d_in[0];
    const int*   T1  = (const int*)d_in[1];
    const int*   T2  = (const int*)d_in[2];
    const float* emb = (const float*)d_in[3];
    const float* W1  = (const float*)d_in[4];
    const float* W2  = (const float*)d_in[5];
    const float* W3  = (const float*)d_in[6];
    float* out = (float*)d_out;
    (void)in_sizes; (void)n_in; (void)out_size;

    __half* PQh; float *B1, *W2t, *comb, *E;
    cudaGetSymbolAddress((void**)&PQh,  g_PQh);
    cudaGetSymbolAddress((void**)&B1,   g_B1);
    cudaGetSymbolAddress((void**)&W2t,  g_W2t);
    cudaGetSymbolAddress((void**)&comb, g_comb);
    cudaGetSymbolAddress((void**)&E,    g_E);

    // 1) weight transposes
    prep_weights<<<512, 256>>>(W1, W2, W3);

    // 2) PQ[100000,512] = emb[100000,256] @ B1[256,512]  (tf32 TC, fp16 out)
    {
        dim3 grid(512 / 128, (NUM_NODES + 127) / 128);
        gemm_tf32<false, 2, __half><<<grid, 256>>>(emb, B1, PQh, NUM_NODES, 512, 256);
    }

    // 3) fused gathers/means/relu -> g_comb [4096, 512]
    gather_fuse<<<BATCH, 128>>>(T0, T1, T2);

    // 4) E = relu(comb @ W2t): [4096,512]x[512,256]  (tf32 TC, BM=64 for 128 CTAs)
    {
        dim3 grid(256 / 128, BATCH / 64);
        gemm_tf32<true, 1, float><<<grid, 256>>>(comb, W2t, E, BATCH, 256, 512);
    }

    // 5) scores = E @ W3t : [4096,256]x[256,64]  (fp32 exact)
    scores_k<<<BATCH / 32, 256>>>(out);
}

// round 4
// speedup vs baseline: 3.3155x; 1.4649x over previous
#include <cuda_runtime.h>
#include <cuda_fp16.h>
#include <cstdint>
#include <cstddef>

#define NUM_NODES 100000
#define FEAT_DIM  256
#define BATCH     4096
#define F1N       25
#define F2N       10

// ---------------- static scratch ----------------
__device__ __half g_embh[(size_t)NUM_NODES * 256];  // fp16 copy of emb
__device__ __half g_Ph[(size_t)NUM_NODES * 256];    // P = emb @ W1[:, :256].T
__device__ __half g_Qh[(size_t)NUM_NODES * 256];    // Q = emb @ W1[:, 256:].T
__device__ __half g_B1h[256 * 512];                 // [K=256][N=512] fp16
__device__ __half g_W2th[512 * 256];                // W2^T fp16
__device__ float  g_W3t[256 * 64];                  // W3^T fp32
__device__ __half g_combh[(size_t)BATCH * 512];     // [h0 | h1] fp16
__device__ float  g_E[(size_t)BATCH * 256];

// ---------------- emb -> fp16 ----------------
__global__ void conv_emb(const float* __restrict__ emb) {
    size_t i = ((size_t)blockIdx.x * blockDim.x + threadIdx.x) * 4;
    float4 v = *reinterpret_cast<const float4*>(emb + i);
    *reinterpret_cast<__half2*>(&g_embh[i])     = __floats2half2_rn(v.x, v.y);
    *reinterpret_cast<__half2*>(&g_embh[i + 2]) = __floats2half2_rn(v.z, v.w);
}

// ---------------- weight prep ----------------
__global__ void prep_weights(const float* __restrict__ W1,
                             const float* __restrict__ W2,
                             const float* __restrict__ W3) {
    int idx = blockIdx.x * blockDim.x + threadIdx.x;
    if (idx < 256 * 512) {   // B1h[k][n]
        int k = idx >> 9, n = idx & 511;
        float v = (n < 256) ? W1[n * 512 + k] : W1[(n - 256) * 512 + 256 + k];
        g_B1h[idx] = __float2half(v);
    }
    if (idx < 512 * 256) {   // W2th[k][n] = W2[n][k]
        int k = idx >> 8, n = idx & 255;
        g_W2th[idx] = __float2half(W2[n * 512 + k]);
    }
    if (idx < 256 * 64) {    // W3t[k][n] = W3[n][k]
        int k = idx >> 6, n = idx & 63;
        g_W3t[idx] = W3[n * 256 + k];
    }
}

// ---------------- fp16 tensor-core GEMM, cp.async 3-stage, ldmatrix ----------------
// C[M,N] = A[M,K] * B[K,N], A/B fp16 row-major, fp32 accum, optional ReLU.
// 256 threads = 8 warps, 4(M) x 2(N); warp tile (MT*16) x 64. BM=MT*64, BN=128, BK=32.
// K % 32 == 0, N % 128 == 0; M tail guarded via cp.async zero-fill + epilogue guard.

__device__ __forceinline__ uint32_t smem_u32(const void* p) {
    return (uint32_t)__cvta_generic_to_shared(p);
}
// A tile: [BM rows][4 chunks of 16B] (32 fp16/row). swizzle keeps ldmatrix conflict-free.
__device__ __forceinline__ uint32_t a_off(int row, int c) {
    return (uint32_t)(row * 64 + ((c ^ ((row >> 1) & 3)) * 16));
}
// B tile: [32 rows (k)][16 chunks of 16B] (128 fp16/row).
__device__ __forceinline__ uint32_t b_off(int k, int c) {
    return (uint32_t)(k * 256 + (((c & 8) | ((c ^ k) & 7)) * 16));
}
__device__ __forceinline__ void cp16(uint32_t dst, const void* src, int pred16) {
    asm volatile("cp.async.cg.shared.global [%0], [%1], 16, %2;"
                 :: "r"(dst), "l"(src), "r"(pred16));
}
__device__ __forceinline__ void ldsm4(uint32_t& r0, uint32_t& r1, uint32_t& r2,
                                      uint32_t& r3, uint32_t a) {
    asm volatile("ldmatrix.sync.aligned.m8n8.x4.shared.b16 {%0,%1,%2,%3}, [%4];"
                 : "=r"(r0), "=r"(r1), "=r"(r2), "=r"(r3) : "r"(a));
}
__device__ __forceinline__ void ldsm4t(uint32_t& r0, uint32_t& r1, uint32_t& r2,
                                       uint32_t& r3, uint32_t a) {
    asm volatile("ldmatrix.sync.aligned.m8n8.x4.trans.shared.b16 {%0,%1,%2,%3}, [%4];"
                 : "=r"(r0), "=r"(r1), "=r"(r2), "=r"(r3) : "r"(a));
}
__device__ __forceinline__ void mma16816(float* d, const uint32_t* a, uint32_t b0,
                                         uint32_t b1) {
    asm volatile(
        "mma.sync.aligned.m16n8k16.row.col.f32.f16.f16.f32 "
        "{%0,%1,%2,%3}, {%4,%5,%6,%7}, {%8,%9}, {%0,%1,%2,%3};\n"
        : "+f"(d[0]), "+f"(d[1]), "+f"(d[2]), "+f"(d[3])
        : "r"(a[0]), "r"(a[1]), "r"(a[2]), "r"(a[3]), "r"(b0), "r"(b1));
}
__device__ __forceinline__ void store2o(float* C, size_t off, float x, float y) {
    *reinterpret_cast<float2*>(C + off) = make_float2(x, y);
}
__device__ __forceinline__ void store2o(__half* C, size_t off, float x, float y) {
    *reinterpret_cast<__half2*>(C + off) = __floats2half2_rn(x, y);
}

template <bool RELU, int MT, typename OutT, bool SPLIT>
__global__ __launch_bounds__(256, 2)
void gemm_f16(const __half* __restrict__ A, const __half* __restrict__ B,
              OutT* __restrict__ C0, OutT* __restrict__ C1, int M, int N, int K) {
    const int BM = MT * 64;
    const int ASZ = BM * 64;              // bytes per A stage
    const int STG = ASZ + 8192;           // bytes per stage (A + B)
    __shared__ __align__(16) char smem[3 * (MT * 64 * 64 + 8192)];

    const int tid  = threadIdx.x;
    const int lane = tid & 31;
    const int wid  = tid >> 5;
    const int warpM = wid & 3;
    const int warpN = wid >> 2;
    const int wbase = warpM * MT * 16;
    const int j8 = lane & 7;              // ldmatrix row-in-group
    const int g8 = lane >> 3;             // ldmatrix group 0..3
    const int m0 = blockIdx.y * BM;
    const int n0 = blockIdx.x * 128;
    const uint32_t sbase = smem_u32(smem);

    float acc[MT][8][4];
#pragma unroll
    for (int mt = 0; mt < MT; mt++)
#pragma unroll
        for (int nt = 0; nt < 8; nt++)
#pragma unroll
            for (int c = 0; c < 4; c++) acc[mt][nt][c] = 0.f;

    const int NK = K / 32;

    // cp.async issue of one stage
    auto issue = [&](int st, int kb) {
        uint32_t as = sbase + st * STG;
        uint32_t bs = as + ASZ;
#pragma unroll
        for (int it = 0; it < MT; it++) {
            int i = tid + it * 256;         // A: BM*4 chunks
            int row = i >> 2, c = i & 3;
            int gm = m0 + row;
            cp16(as + a_off(row, c), A + (size_t)gm * K + kb + c * 8,
                 (gm < M) ? 16 : 0);
        }
#pragma unroll
        for (int it = 0; it < 2; it++) {
            int i = tid + it * 256;         // B: 32*16 chunks
            int k = i >> 4, c = i & 15;
            cp16(bs + b_off(k, c), B + (size_t)(kb + k) * N + n0 + c * 8, 16);
        }
    };

    issue(0, 0);
    asm volatile("cp.async.commit_group;");
    if (NK > 1) issue(1, 32);
    asm volatile("cp.async.commit_group;");

    for (int i = 0; i < NK; i++) {
        asm volatile("cp.async.wait_group 1;");
        __syncthreads();
        if (i + 2 < NK) issue((i + 2) % 3, (i + 2) * 32);
        asm volatile("cp.async.commit_group;");

        uint32_t as = sbase + (i % 3) * STG;
        uint32_t bs = as + ASZ;
#pragma unroll
        for (int kk = 0; kk < 2; kk++) {
            uint32_t afr[MT][4];
#pragma unroll
            for (int mt = 0; mt < MT; mt++) {
                int row = wbase + mt * 16 + (g8 & 1) * 8 + j8;
                int ch  = kk * 2 + (g8 >> 1);
                ldsm4(afr[mt][0], afr[mt][1], afr[mt][2], afr[mt][3],
                      as + a_off(row, ch));
            }
#pragma unroll
            for (int nt2 = 0; nt2 < 4; nt2++) {
                int kb = kk * 16 + (g8 & 1) * 8 + j8;
                int cb = ((warpN * 64 + nt2 * 16) >> 3) + (g8 >> 1);
                uint32_t b0, b1, b2, b3;
                ldsm4t(b0, b1, b2, b3, bs + b_off(kb, cb));
#pragma unroll
                for (int mt = 0; mt < MT; mt++) {
                    mma16816(acc[mt][nt2 * 2 + 0], afr[mt], b0, b1);
                    mma16816(acc[mt][nt2 * 2 + 1], afr[mt], b2, b3);
                }
            }
        }
        __syncthreads();
    }

    // epilogue
    const int gid = lane >> 2, lg = lane & 3;
    OutT* Cp = C0;
    int nbase = n0, Nout = N;
    if (SPLIT) {
        Nout = 256;
        if (n0 >= 256) { Cp = C1; nbase = n0 - 256; }
    }
#pragma unroll
    for (int mt = 0; mt < MT; mt++) {
        int r0 = m0 + wbase + mt * 16 + gid;
#pragma unroll
        for (int half = 0; half < 2; half++) {
            int gm = r0 + half * 8;
            if (gm >= M) continue;
#pragma unroll
            for (int nt = 0; nt < 8; nt++) {
                float x = acc[mt][nt][half * 2 + 0];
                float y = acc[mt][nt][half * 2 + 1];
                if (RELU) { x = fmaxf(x, 0.f); y = fmaxf(y, 0.f); }
                int col = nbase + warpN * 64 + nt * 8 + lg * 2;
                store2o(Cp, (size_t)gm * Nout + col, x, y);
            }
        }
    }
}

// ---------------- fused gather / mean / relu (fp16 P/Q, half2 lanes) ----------------
__global__ __launch_bounds__(128)
void gather_fuse(const int* __restrict__ T0, const int* __restrict__ T1,
                 const int* __restrict__ T2) {
    int b = blockIdx.x;
    int d2 = threadIdx.x;
    __shared__ int sT1[F1N];
    __shared__ int sT2[F1N * F2N];
    if (d2 < F1N) sT1[d2] = T1[b * F1N + d2];
    for (int i = d2; i < F1N * F2N; i += 128) sT2[i] = T2[b * F1N * F2N + i];
    __syncthreads();

    const __half2* __restrict__ P2 = reinterpret_cast<const __half2*>(g_Ph);
    const __half2* __restrict__ Q2 = reinterpret_cast<const __half2*>(g_Qh);
    float qx = 0.f, qy = 0.f, hx = 0.f, hy = 0.f;
#pragma unroll 1
    for (int i = 0; i < F1N; i++) {
        size_t m = (size_t)sT1[i] * 128;
        float2 q = __half22float2(Q2[m + d2]);
        qx += q.x; qy += q.y;
        float2 p = __half22float2(P2[m + d2]);
        float sx = 0.f, sy = 0.f;
#pragma unroll
        for (int j = 0; j < F2N; j++) {
            float2 v = __half22float2(Q2[(size_t)sT2[i * F2N + j] * 128 + d2]);
            sx += v.x; sy += v.y;
        }
        hx += fmaxf(fmaf(sx, 1.f / F2N, p.x), 0.f);
        hy += fmaxf(fmaf(sy, 1.f / F2N, p.y), 0.f);
    }
    float2 p0 = __half22float2(P2[(size_t)T0[b] * 128 + d2]);
    float h0x = fmaxf(fmaf(qx, 1.f / F1N, p0.x), 0.f);
    float h0y = fmaxf(fmaf(qy, 1.f / F1N, p0.y), 0.f);
    __half2* C2 = reinterpret_cast<__half2*>(g_combh);
    C2[(size_t)b * 256 + d2]       = __floats2half2_rn(h0x, h0y);
    C2[(size_t)b * 256 + 128 + d2] = __floats2half2_rn(hx * (1.f / F1N), hy * (1.f / F1N));
}

// ---------------- scores: 32 batch rows per block, E staged in smem ----------------
__global__ __launch_bounds__(256)
void scores_k(float* __restrict__ out) {
    int b0 = blockIdx.x * 32;
    __shared__ float sE[32 * 257];
    int tid = threadIdx.x;
#pragma unroll
    for (int it = 0; it < 8; it++) {
        int i = tid + it * 256;
        int r = i >> 6, k4 = (i & 63) * 4;
        float4 v = *reinterpret_cast<const float4*>(&g_E[(size_t)(b0 + r) * 256 + k4]);
        float* p = &sE[r * 257 + k4];
        p[0] = v.x; p[1] = v.y; p[2] = v.z; p[3] = v.w;
    }
    __syncthreads();

    int col = tid & 63, rg = tid >> 6;
    float a[8];
#pragma unroll
    for (int i = 0; i < 8; i++) a[i] = 0.f;
#pragma unroll 4
    for (int k = 0; k < 256; k++) {
        float w = g_W3t[k * 64 + col];
        const float* pe = &sE[(rg * 8) * 257 + k];
#pragma unroll
        for (int i = 0; i < 8; i++) a[i] = fmaf(pe[i * 257], w, a[i]);
    }
#pragma unroll
    for (int i = 0; i < 8; i++)
        out[(size_t)(b0 + rg * 8 + i) * 64 + col] = a[i];
}

// ---------------- launch ----------------
extern "C" void kernel_launch(void* const* d_in, const int* in_sizes, int n_in,
                              void* d_out, int out_size) {
    const int*   T0  = (const int*)d_in[0];
    const int*   T1  = (const int*)d_in[1];
    const int*   T2  = (const int*)d_in[2];
    const float* emb = (const float*)d_in[3];
    const float* W1  = (const float*)d_in[4];
    const float* W2  = (const float*)d_in[5];
    const float* W3  = (const float*)d_in[6];
    float* out = (float*)d_out;
    (void)in_sizes; (void)n_in; (void)out_size;

    __half *embh, *Ph, *Qh, *B1h, *W2th, *combh;
    float* E;
    cudaGetSymbolAddress((void**)&embh,  g_embh);
    cudaGetSymbolAddress((void**)&Ph,    g_Ph);
    cudaGetSymbolAddress((void**)&Qh,    g_Qh);
    cudaGetSymbolAddress((void**)&B1h,   g_B1h);
    cudaGetSymbolAddress((void**)&W2th,  g_W2th);
    cudaGetSymbolAddress((void**)&combh, g_combh);
    cudaGetSymbolAddress((void**)&E,     g_E);

    // 1) conversions / weight prep
    conv_emb<<<(NUM_NODES * 256 / 4 + 255) / 256, 256>>>(emb);
    prep_weights<<<512, 256>>>(W1, W2, W3);

    // 2) [P|Q] = embh @ B1h : [100000,256]x[256,512], split outputs (fp16)
    {
        dim3 grid(4, (NUM_NODES + 127) / 128);
        gemm_f16<false, 2, __half, true><<<grid, 256>>>(
            embh, B1h, Ph, Qh, NUM_NODES, 512, 256);
    }

    // 3) fused gathers/means/relu -> g_combh [4096, 512] fp16
    gather_fuse<<<BATCH, 128>>>(T0, T1, T2);

    // 4) E = relu(combh @ W2th): [4096,512]x[512,256] fp32 out, BM=64
    {
        dim3 grid(2, BATCH / 64);
        gemm_f16<true, 1, float, false><<<grid, 256>>>(
            combh, W2th, E, E, BATCH, 256, 512);
    }

    // 5) scores = E @ W3t (fp32 exact)
    scores_k<<<BATCH / 32, 256>>>(out);
}

// round 6
// speedup vs baseline: 3.8171x; 1.1513x over previous
#include <cuda_runtime.h>
#include <cuda_fp16.h>
#include <cstdint>
#include <cstddef>

#define NUM_NODES 100000
#define FEAT_DIM  256
#define BATCH     4096
#define F1N       25
#define F2N       10

// ---------------- static scratch ----------------
__device__ __half g_embh[(size_t)NUM_NODES * 256];  // fp16 copy of emb
__device__ __half g_Ph[(size_t)NUM_NODES * 256];    // P = emb @ W1[:, :256].T
__device__ __half g_Qh[(size_t)NUM_NODES * 256];    // Q = emb @ W1[:, 256:].T
__device__ __half g_B1h[256 * 512];                 // [K=256][N=512] fp16
__device__ __half g_W2th[512 * 256];                // W2^T fp16
__device__ float  g_W3t[256 * 64];                  // W3^T fp32
__device__ __half g_combh[(size_t)BATCH * 512];     // [h0 | h1] fp16
__device__ float  g_E[(size_t)BATCH * 256];

// ---------------- emb -> fp16 ----------------
__global__ void conv_emb(const float* __restrict__ emb) {
    size_t i = ((size_t)blockIdx.x * blockDim.x + threadIdx.x) * 4;
    float4 v = *reinterpret_cast<const float4*>(emb + i);
    *reinterpret_cast<__half2*>(&g_embh[i])     = __floats2half2_rn(v.x, v.y);
    *reinterpret_cast<__half2*>(&g_embh[i + 2]) = __floats2half2_rn(v.z, v.w);
}

// ---------------- weight prep ----------------
__global__ void prep_weights(const float* __restrict__ W1,
                             const float* __restrict__ W2,
                             const float* __restrict__ W3) {
    int idx = blockIdx.x * blockDim.x + threadIdx.x;
    if (idx < 256 * 512) {   // B1h[k][n]
        int k = idx >> 9, n = idx & 511;
        float v = (n < 256) ? W1[n * 512 + k] : W1[(n - 256) * 512 + 256 + k];
        g_B1h[idx] = __float2half(v);
    }
    if (idx < 512 * 256) {   // W2th[k][n] = W2[n][k]
        int k = idx >> 8, n = idx & 255;
        g_W2th[idx] = __float2half(W2[n * 512 + k]);
    }
    if (idx < 256 * 64) {    // W3t[k][n] = W3[n][k]
        int k = idx >> 6, n = idx & 63;
        g_W3t[idx] = W3[n * 256 + k];
    }
}

// ---------------- fp16 tensor-core GEMM, cp.async 3-stage, ldmatrix ----------------
__device__ __forceinline__ uint32_t smem_u32(const void* p) {
    return (uint32_t)__cvta_generic_to_shared(p);
}
__device__ __forceinline__ uint32_t a_off(int row, int c) {
    return (uint32_t)(row * 64 + ((c ^ ((row >> 1) & 3)) * 16));
}
__device__ __forceinline__ uint32_t b_off(int k, int c) {
    return (uint32_t)(k * 256 + (((c & 8) | ((c ^ k) & 7)) * 16));
}
__device__ __forceinline__ void cp16(uint32_t dst, const void* src, int pred16) {
    asm volatile("cp.async.cg.shared.global [%0], [%1], 16, %2;"
                 :: "r"(dst), "l"(src), "r"(pred16));
}
__device__ __forceinline__ void ldsm4(uint32_t& r0, uint32_t& r1, uint32_t& r2,
                                      uint32_t& r3, uint32_t a) {
    asm volatile("ldmatrix.sync.aligned.m8n8.x4.shared.b16 {%0,%1,%2,%3}, [%4];"
                 : "=r"(r0), "=r"(r1), "=r"(r2), "=r"(r3) : "r"(a));
}
__device__ __forceinline__ void ldsm4t(uint32_t& r0, uint32_t& r1, uint32_t& r2,
                                       uint32_t& r3, uint32_t a) {
    asm volatile("ldmatrix.sync.aligned.m8n8.x4.trans.shared.b16 {%0,%1,%2,%3}, [%4];"
                 : "=r"(r0), "=r"(r1), "=r"(r2), "=r"(r3) : "r"(a));
}
__device__ __forceinline__ void mma16816(float* d, const uint32_t* a, uint32_t b0,
                                         uint32_t b1) {
    asm volatile(
        "mma.sync.aligned.m16n8k16.row.col.f32.f16.f16.f32 "
        "{%0,%1,%2,%3}, {%4,%5,%6,%7}, {%8,%9}, {%0,%1,%2,%3};\n"
        : "+f"(d[0]), "+f"(d[1]), "+f"(d[2]), "+f"(d[3])
        : "r"(a[0]), "r"(a[1]), "r"(a[2]), "r"(a[3]), "r"(b0), "r"(b1));
}
__device__ __forceinline__ void store2o(float* C, size_t off, float x, float y) {
    *reinterpret_cast<float2*>(C + off) = make_float2(x, y);
}
__device__ __forceinline__ void store2o(__half* C, size_t off, float x, float y) {
    *reinterpret_cast<__half2*>(C + off) = __floats2half2_rn(x, y);
}

template <bool RELU, int MT, typename OutT, bool SPLIT>
__global__ __launch_bounds__(256, 2)
void gemm_f16(const __half* __restrict__ A, const __half* __restrict__ B,
              OutT* __restrict__ C0, OutT* __restrict__ C1, int M, int N, int K) {
    const int BM = MT * 64;
    const int ASZ = BM * 64;
    const int STG = ASZ + 8192;
    __shared__ __align__(16) char smem[3 * (MT * 64 * 64 + 8192)];

    const int tid  = threadIdx.x;
    const int lane = tid & 31;
    const int wid  = tid >> 5;
    const int warpM = wid & 3;
    const int warpN = wid >> 2;
    const int wbase = warpM * MT * 16;
    const int j8 = lane & 7;
    const int g8 = lane >> 3;
    const int m0 = blockIdx.y * BM;
    const int n0 = blockIdx.x * 128;
    const uint32_t sbase = smem_u32(smem);

    float acc[MT][8][4];
#pragma unroll
    for (int mt = 0; mt < MT; mt++)
#pragma unroll
        for (int nt = 0; nt < 8; nt++)
#pragma unroll
            for (int c = 0; c < 4; c++) acc[mt][nt][c] = 0.f;

    const int NK = K / 32;

    auto issue = [&](int st, int kb) {
        uint32_t as = sbase + st * STG;
        uint32_t bs = as + ASZ;
#pragma unroll
        for (int it = 0; it < MT; it++) {
            int i = tid + it * 256;
            int row = i >> 2, c = i & 3;
            int gm = m0 + row;
            cp16(as + a_off(row, c), A + (size_t)gm * K + kb + c * 8,
                 (gm < M) ? 16 : 0);
        }
#pragma unroll
        for (int it = 0; it < 2; it++) {
            int i = tid + it * 256;
            int k = i >> 4, c = i & 15;
            cp16(bs + b_off(k, c), B + (size_t)(kb + k) * N + n0 + c * 8, 16);
        }
    };

    issue(0, 0);
    asm volatile("cp.async.commit_group;");
    if (NK > 1) issue(1, 32);
    asm volatile("cp.async.commit_group;");

    for (int i = 0; i < NK; i++) {
        asm volatile("cp.async.wait_group 1;");
        __syncthreads();
        if (i + 2 < NK) issue((i + 2) % 3, (i + 2) * 32);
        asm volatile("cp.async.commit_group;");

        uint32_t as = sbase + (i % 3) * STG;
        uint32_t bs = as + ASZ;
#pragma unroll
        for (int kk = 0; kk < 2; kk++) {
            uint32_t afr[MT][4];
#pragma unroll
            for (int mt = 0; mt < MT; mt++) {
                int row = wbase + mt * 16 + (g8 & 1) * 8 + j8;
                int ch  = kk * 2 + (g8 >> 1);
                ldsm4(afr[mt][0], afr[mt][1], afr[mt][2], afr[mt][3],
                      as + a_off(row, ch));
            }
#pragma unroll
            for (int nt2 = 0; nt2 < 4; nt2++) {
                int kb = kk * 16 + (g8 & 1) * 8 + j8;
                int cb = ((warpN * 64 + nt2 * 16) >> 3) + (g8 >> 1);
                uint32_t b0, b1, b2, b3;
                ldsm4t(b0, b1, b2, b3, bs + b_off(kb, cb));
#pragma unroll
                for (int mt = 0; mt < MT; mt++) {
                    mma16816(acc[mt][nt2 * 2 + 0], afr[mt], b0, b1);
                    mma16816(acc[mt][nt2 * 2 + 1], afr[mt], b2, b3);
                }
            }
        }
        __syncthreads();
    }

    const int gid = lane >> 2, lg = lane & 3;
    OutT* Cp = C0;
    int nbase = n0, Nout = N;
    if (SPLIT) {
        Nout = 256;
        if (n0 >= 256) { Cp = C1; nbase = n0 - 256; }
    }
#pragma unroll
    for (int mt = 0; mt < MT; mt++) {
        int r0 = m0 + wbase + mt * 16 + gid;
#pragma unroll
        for (int half = 0; half < 2; half++) {
            int gm = r0 + half * 8;
            if (gm >= M) continue;
#pragma unroll
            for (int nt = 0; nt < 8; nt++) {
                float x = acc[mt][nt][half * 2 + 0];
                float y = acc[mt][nt][half * 2 + 1];
                if (RELU) { x = fmaxf(x, 0.f); y = fmaxf(y, 0.f); }
                int col = nbase + warpN * 64 + nt * 8 + lg * 2;
                store2o(Cp, (size_t)gm * Nout + col, x, y);
            }
        }
    }
}

// ---------------- fused gather / mean / relu — v2 (alignment-fixed) ----------------
// 128 threads = 4 warps per batch row. Lane owns 8 dims (one uint4 = 8 halves).
// Warp w handles neighbors i = w, w+4, ...; fp32 partials reduced via smem.
// Inner 10-way j-sum is an fp16 __hadd2 chain.
// NOTE: sH/sQ are declared FIRST with __align__(16) — the float4 partial stores
// require 16B alignment; in Round 5 they sat after the int index arrays at
// offset 1100 and crashed with "misaligned address".
__global__ __launch_bounds__(128)
void gather_fuse(const int* __restrict__ T0, const int* __restrict__ T1,
                 const int* __restrict__ T2) {
    const int b = blockIdx.x;
    const int tid = threadIdx.x;
    const int lane = tid & 31;
    const int w = tid >> 5;

    __shared__ __align__(16) float sH[4 * 256];
    __shared__ __align__(16) float sQ[4 * 256];
    __shared__ int sT1[F1N];
    __shared__ int sT2[F1N * F2N];

    if (tid < F1N) sT1[tid] = T1[b * F1N + tid];
    for (int i = tid; i < F1N * F2N; i += 128) sT2[i] = T2[b * F1N * F2N + i];
    __syncthreads();

    const uint4* __restrict__ Pv = reinterpret_cast<const uint4*>(g_Ph);
    const uint4* __restrict__ Qv = reinterpret_cast<const uint4*>(g_Qh);

    float hacc[8], qacc[8];
#pragma unroll
    for (int c = 0; c < 8; c++) { hacc[c] = 0.f; qacc[c] = 0.f; }

    for (int i = w; i < F1N; i += 4) {
        const int n1 = sT1[i];
        uint4 pr = Pv[(size_t)n1 * 32 + lane];
        uint4 qr = Qv[(size_t)n1 * 32 + lane];

        // fp16 chain sum of 10 Q rows
        uint4 a0 = Qv[(size_t)sT2[i * F2N + 0] * 32 + lane];
        __half2 s0 = ((const __half2*)&a0)[0];
        __half2 s1 = ((const __half2*)&a0)[1];
        __half2 s2 = ((const __half2*)&a0)[2];
        __half2 s3 = ((const __half2*)&a0)[3];
#pragma unroll
        for (int j = 1; j < F2N; j++) {
            uint4 aj = Qv[(size_t)sT2[i * F2N + j] * 32 + lane];
            s0 = __hadd2(s0, ((const __half2*)&aj)[0]);
            s1 = __hadd2(s1, ((const __half2*)&aj)[1]);
            s2 = __hadd2(s2, ((const __half2*)&aj)[2]);
            s3 = __hadd2(s3, ((const __half2*)&aj)[3]);
        }
        __half2 sv[4] = {s0, s1, s2, s3};
#pragma unroll
        for (int c = 0; c < 4; c++) {
            float2 sf = __half22float2(sv[c]);
            float2 pf = __half22float2(((const __half2*)&pr)[c]);
            float2 qf = __half22float2(((const __half2*)&qr)[c]);
            qacc[2 * c + 0] += qf.x;
            qacc[2 * c + 1] += qf.y;
            hacc[2 * c + 0] += fmaxf(fmaf(sf.x, 1.f / F2N, pf.x), 0.f);
            hacc[2 * c + 1] += fmaxf(fmaf(sf.y, 1.f / F2N, pf.y), 0.f);
        }
    }

    // write partials (two float4 per lane per array; 16B-aligned by layout)
    {
        float* ph = &sH[w * 256 + lane * 8];
        float* pq = &sQ[w * 256 + lane * 8];
        *reinterpret_cast<float4*>(ph)     = make_float4(hacc[0], hacc[1], hacc[2], hacc[3]);
        *reinterpret_cast<float4*>(ph + 4) = make_float4(hacc[4], hacc[5], hacc[6], hacc[7]);
        *reinterpret_cast<float4*>(pq)     = make_float4(qacc[0], qacc[1], qacc[2], qacc[3]);
        *reinterpret_cast<float4*>(pq + 4) = make_float4(qacc[4], qacc[5], qacc[6], qacc[7]);
    }
    __syncthreads();

    // reduction: thread t -> dims {2t, 2t+1}
    float hx = 0.f, hy = 0.f, qx = 0.f, qy = 0.f;
#pragma unroll
    for (int ww = 0; ww < 4; ww++) {
        float2 hv = *reinterpret_cast<const float2*>(&sH[ww * 256 + 2 * tid]);
        float2 qv = *reinterpret_cast<const float2*>(&sQ[ww * 256 + 2 * tid]);
        hx += hv.x; hy += hv.y;
        qx += qv.x; qy += qv.y;
    }
    float2 p0 = __half22float2(
        reinterpret_cast<const __half2*>(g_Ph)[(size_t)T0[b] * 128 + tid]);
    float h0x = fmaxf(fmaf(qx, 1.f / F1N, p0.x), 0.f);
    float h0y = fmaxf(fmaf(qy, 1.f / F1N, p0.y), 0.f);
    __half2* C2 = reinterpret_cast<__half2*>(g_combh);
    C2[(size_t)b * 256 + tid]       = __floats2half2_rn(h0x, h0y);
    C2[(size_t)b * 256 + 128 + tid] = __floats2half2_rn(hx * (1.f / F1N), hy * (1.f / F1N));
}

// ---------------- scores: 32 batch rows per block, E staged in smem ----------------
__global__ __launch_bounds__(256)
void scores_k(float* __restrict__ out) {
    int b0 = blockIdx.x * 32;
    __shared__ __align__(16) float sE[32 * 257];
    int tid = threadIdx.x;
#pragma unroll
    for (int it = 0; it < 8; it++) {
        int i = tid + it * 256;
        int r = i >> 6, k4 = (i & 63) * 4;
        float4 v = *reinterpret_cast<const float4*>(&g_E[(size_t)(b0 + r) * 256 + k4]);
        float* p = &sE[r * 257 + k4];
        p[0] = v.x; p[1] = v.y; p[2] = v.z; p[3] = v.w;
    }
    __syncthreads();

    int col = tid & 63, rg = tid >> 6;
    float a[8];
#pragma unroll
    for (int i = 0; i < 8; i++) a[i] = 0.f;
#pragma unroll 4
    for (int k = 0; k < 256; k++) {
        float w = g_W3t[k * 64 + col];
        const float* pe = &sE[(rg * 8) * 257 + k];
#pragma unroll
        for (int i = 0; i < 8; i++) a[i] = fmaf(pe[i * 257], w, a[i]);
    }
#pragma unroll
    for (int i = 0; i < 8; i++)
        out[(size_t)(b0 + rg * 8 + i) * 64 + col] = a[i];
}

// ---------------- launch ----------------
extern "C" void kernel_launch(void* const* d_in, const int* in_sizes, int n_in,
                              void* d_out, int out_size) {
    const int*   T0  = (const int*)d_in[0];
    const int*   T1  = (const int*)d_in[1];
    const int*   T2  = (const int*)d_in[2];
    const float* emb = (const float*)d_in[3];
    const float* W1  = (const float*)d_in[4];
    const float* W2  = (const float*)d_in[5];
    const float* W3  = (const float*)d_in[6];
    float* out = (float*)d_out;
    (void)in_sizes; (void)n_in; (void)out_size;

    __half *embh, *Ph, *Qh, *B1h, *W2th, *combh;
    float* E;
    cudaGetSymbolAddress((void**)&embh,  g_embh);
    cudaGetSymbolAddress((void**)&Ph,    g_Ph);
    cudaGetSymbolAddress((void**)&Qh,    g_Qh);
    cudaGetSymbolAddress((void**)&B1h,   g_B1h);
    cudaGetSymbolAddress((void**)&W2th,  g_W2th);
    cudaGetSymbolAddress((void**)&combh, g_combh);
    cudaGetSymbolAddress((void**)&E,     g_E);

    // 1) conversions / weight prep
    conv_emb<<<(NUM_NODES * 256 / 4 + 255) / 256, 256>>>(emb);
    prep_weights<<<512, 256>>>(W1, W2, W3);

    // 2) [P|Q] = embh @ B1h : [100000,256]x[256,512], split outputs (fp16)
    {
        dim3 grid(4, (NUM_NODES + 127) / 128);
        gemm_f16<false, 2, __half, true><<<grid, 256>>>(
            embh, B1h, Ph, Qh, NUM_NODES, 512, 256);
    }

    // 3) fused gathers/means/relu -> g_combh [4096, 512] fp16
    gather_fuse<<<BATCH, 128>>>(T0, T1, T2);

    // 4) E = relu(combh @ W2th): [4096,512]x[512,256] fp32 out, BM=64
    {
        dim3 grid(2, BATCH / 64);
        gemm_f16<true, 1, float, false><<<grid, 256>>>(
            combh, W2th, E, E, BATCH, 256, 512);
    }

    // 5) scores = E @ W3t (fp32 exact)
    scores_k<<<BATCH / 32, 256>>>(out);
}

// round 10
// speedup vs baseline: 4.0241x; 1.0542x over previous
#include <cuda_runtime.h>
#include <cuda_fp16.h>
#include <cstdint>
#include <cstddef>

#define NUM_NODES 100000
#define FEAT_DIM  256
#define BATCH     4096
#define F1N       25
#define F2N       10

// ---------------- static scratch ----------------
__device__ __half g_embh[(size_t)NUM_NODES * 256];  // fp16 copy of emb
__device__ __half g_Ph[(size_t)NUM_NODES * 256];    // P = emb @ W1[:, :256].T
__device__ __half g_Qh[(size_t)NUM_NODES * 256];    // Q = emb @ W1[:, 256:].T
__device__ __half g_B1h[256 * 512];                 // [K=256][N=512] fp16
__device__ __half g_W2th[512 * 256];                // W2^T fp16 [k][n]
__device__ float  g_W3t[256 * 64];                  // W3^T fp32
__device__ __half g_combh[(size_t)BATCH * 512];     // [h0 | h1] fp16
__device__ float  g_E[(size_t)BATCH * 256];

// ---------------- emb -> fp16 ----------------
__global__ void conv_emb(const float* __restrict__ emb) {
    size_t i = ((size_t)blockIdx.x * blockDim.x + threadIdx.x) * 4;
    float4 v = *reinterpret_cast<const float4*>(emb + i);
    *reinterpret_cast<__half2*>(&g_embh[i])     = __floats2half2_rn(v.x, v.y);
    *reinterpret_cast<__half2*>(&g_embh[i + 2]) = __floats2half2_rn(v.z, v.w);
}

// ---------------- weight prep ----------------
__global__ void prep_weights(const float* __restrict__ W1,
                             const float* __restrict__ W2,
                             const float* __restrict__ W3) {
    int idx = blockIdx.x * blockDim.x + threadIdx.x;
    if (idx < 256 * 512) {   // B1h[k][n]
        int k = idx >> 9, n = idx & 511;
        float v = (n < 256) ? W1[n * 512 + k] : W1[(n - 256) * 512 + 256 + k];
        g_B1h[idx] = __float2half(v);
    }
    if (idx < 512 * 256) {   // W2th[k][n] = W2[n][k]
        int k = idx >> 8, n = idx & 255;
        g_W2th[idx] = __float2half(W2[n * 512 + k]);
    }
    if (idx < 256 * 64) {    // W3t[k][n] = W3[n][k]
        int k = idx >> 6, n = idx & 63;
        g_W3t[idx] = W3[n * 256 + k];
    }
}

// ---------------- fp16 tensor-core GEMM, BK=64, 2-stage cp.async ----------------
// C[M,N] = A[M,K] * B[K,N]; A/B fp16 row-major; fp32 accum; optional ReLU;
// optional SPLIT (cols [0,256)->C0, [256,512)->C1, each 256-wide).
// 256 threads = 8 warps, 4(M) x 2(N); warp tile (MT*16) x 64. BM=MT*64, BN=128.
// K % 64 == 0, N % 128 == 0; M tail guarded.
//
// Smem tiles (per stage):
//   A: BM rows x 64 halves (128 B/row, 8 chunks of 16B), chunk swizzle c ^ (r&7)
//   B: 64 rows (k) x 128 halves (256 B/row, 16 chunks), swizzle (c&8)|((c^k)&7)

__device__ __forceinline__ uint32_t smem_u32(const void* p) {
    return (uint32_t)__cvta_generic_to_shared(p);
}
__device__ __forceinline__ uint32_t a2_off(int row, int c) {
    return (uint32_t)(row * 128 + ((c ^ (row & 7)) * 16));
}
__device__ __forceinline__ uint32_t b2_off(int k, int c) {
    return (uint32_t)(k * 256 + (((c & 8) | ((c ^ k) & 7)) * 16));
}
__device__ __forceinline__ void cp16(uint32_t dst, const void* src, int pred16) {
    asm volatile("cp.async.cg.shared.global [%0], [%1], 16, %2;"
                 :: "r"(dst), "l"(src), "r"(pred16));
}
__device__ __forceinline__ void ldsm4(uint32_t& r0, uint32_t& r1, uint32_t& r2,
                                      uint32_t& r3, uint32_t a) {
    asm volatile("ldmatrix.sync.aligned.m8n8.x4.shared.b16 {%0,%1,%2,%3}, [%4];"
                 : "=r"(r0), "=r"(r1), "=r"(r2), "=r"(r3) : "r"(a));
}
__device__ __forceinline__ void ldsm4t(uint32_t& r0, uint32_t& r1, uint32_t& r2,
                                       uint32_t& r3, uint32_t a) {
    asm volatile("ldmatrix.sync.aligned.m8n8.x4.trans.shared.b16 {%0,%1,%2,%3}, [%4];"
                 : "=r"(r0), "=r"(r1), "=r"(r2), "=r"(r3) : "r"(a));
}
__device__ __forceinline__ void mma16816(float* d, const uint32_t* a, uint32_t b0,
                                         uint32_t b1) {
    asm volatile(
        "mma.sync.aligned.m16n8k16.row.col.f32.f16.f16.f32 "
        "{%0,%1,%2,%3}, {%4,%5,%6,%7}, {%8,%9}, {%0,%1,%2,%3};\n"
        : "+f"(d[0]), "+f"(d[1]), "+f"(d[2]), "+f"(d[3])
        : "r"(a[0]), "r"(a[1]), "r"(a[2]), "r"(a[3]), "r"(b0), "r"(b1));
}
__device__ __forceinline__ void store2o(float* C, size_t off, float x, float y) {
    *reinterpret_cast<float2*>(C + off) = make_float2(x, y);
}
__device__ __forceinline__ void store2o(__half* C, size_t off, float x, float y) {
    *reinterpret_cast<__half2*>(C + off) = __floats2half2_rn(x, y);
}

template <bool RELU, int MT, typename OutT, bool SPLIT>
__global__ __launch_bounds__(256, 2)
void gemm_f16(const __half* __restrict__ A, const __half* __restrict__ B,
              OutT* __restrict__ C0, OutT* __restrict__ C1, int M, int N, int K) {
    const int BM  = MT * 64;
    const int ASZ = BM * 128;              // bytes per A stage (BM rows x 128B)
    const int BSZ = 64 * 256;              // bytes per B stage
    const int STG = ASZ + BSZ;
    extern __shared__ __align__(16) char smem[];

    const int tid  = threadIdx.x;
    const int lane = tid & 31;
    const int wid  = tid >> 5;
    const int warpM = wid & 3;
    const int warpN = wid >> 2;
    const int wbase = warpM * MT * 16;
    const int j8 = lane & 7;
    const int g8 = lane >> 3;
    const int m0 = blockIdx.y * BM;
    const int n0 = blockIdx.x * 128;
    const uint32_t sbase = smem_u32(smem);

    float acc[MT][8][4];
#pragma unroll
    for (int mt = 0; mt < MT; mt++)
#pragma unroll
        for (int nt = 0; nt < 8; nt++)
#pragma unroll
            for (int c = 0; c < 4; c++) acc[mt][nt][c] = 0.f;

    const int NK = K / 64;

    // issue one 64-wide K stage into buffer (s & 1)
    auto issue = [&](int s) {
        const uint32_t as = sbase + (s & 1) * STG;
        const uint32_t bs = as + ASZ;
        const int kb = s * 64;
        // A: BM rows x 8 chunks = MT*512 chunks / 256 threads = MT*2 iterations.
        // (R9 bug: this bound was MT*4, overflowing the A region into B.)
#pragma unroll
        for (int it = 0; it < MT * 2; it++) {
            int i = tid + it * 256;
            int row = i >> 3, c = i & 7;
            int gm = m0 + row;
            cp16(as + a2_off(row, c), A + (size_t)gm * K + kb + c * 8,
                 (gm < M) ? 16 : 0);
        }
#pragma unroll
        for (int it = 0; it < 4; it++) {        // B: 64*16 chunks / 256 thr
            int i = tid + it * 256;
            int k = i >> 4, c = i & 15;
            cp16(bs + b2_off(k, c), B + (size_t)(kb + k) * N + n0 + c * 8, 16);
        }
        asm volatile("cp.async.commit_group;");
    };

    issue(0);
    for (int i = 0; i < NK; i++) {
        if (i + 1 < NK) {
            issue(i + 1);
            asm volatile("cp.async.wait_group 1;");
        } else {
            asm volatile("cp.async.wait_group 0;");
        }
        __syncthreads();

        const uint32_t as = sbase + (i & 1) * STG;
        const uint32_t bs = as + ASZ;
#pragma unroll
        for (int kk = 0; kk < 4; kk++) {
            uint32_t afr[MT][4];
#pragma unroll
            for (int mt = 0; mt < MT; mt++) {
                int row = wbase + mt * 16 + (g8 & 1) * 8 + j8;
                int ch  = kk * 2 + (g8 >> 1);
                ldsm4(afr[mt][0], afr[mt][1], afr[mt][2], afr[mt][3],
                      as + a2_off(row, ch));
            }
#pragma unroll
            for (int nt2 = 0; nt2 < 4; nt2++) {
                int kb = kk * 16 + (g8 & 1) * 8 + j8;
                int cb = ((warpN * 64 + nt2 * 16) >> 3) + (g8 >> 1);
                uint32_t b0, b1, b2, b3;
                ldsm4t(b0, b1, b2, b3, bs + b2_off(kb, cb));
#pragma unroll
                for (int mt = 0; mt < MT; mt++) {
                    mma16816(acc[mt][nt2 * 2 + 0], afr[mt], b0, b1);
                    mma16816(acc[mt][nt2 * 2 + 1], afr[mt], b2, b3);
                }
            }
        }
        __syncthreads();
    }

    // epilogue
    const int gid = lane >> 2, lg = lane & 3;
    OutT* Cp = C0;
    int nbase = n0, Nout = N;
    if (SPLIT) {
        Nout = 256;
        if (n0 >= 256) { Cp = C1; nbase = n0 - 256; }
    }
#pragma unroll
    for (int mt = 0; mt < MT; mt++) {
        int r0 = m0 + wbase + mt * 16 + gid;
#pragma unroll
        for (int half = 0; half < 2; half++) {
            int gm = r0 + half * 8;
            if (gm >= M) continue;
#pragma unroll
            for (int nt = 0; nt < 8; nt++) {
                float x = acc[mt][nt][half * 2 + 0];
                float y = acc[mt][nt][half * 2 + 1];
                if (RELU) { x = fmaxf(x, 0.f); y = fmaxf(y, 0.f); }
                int col = nbase + warpN * 64 + nt * 8 + lg * 2;
                store2o(Cp, (size_t)gm * Nout + col, x, y);
            }
        }
    }
}

#define SMEM_PQ (2 * (128 * 128 + 64 * 256))   // 65536 B  (MT=2)
#define SMEM_W2 (2 * (64 * 128 + 64 * 256))    // 49152 B  (MT=1)

// ---------------- fused gather / mean / relu (unchanged from R6) ----------------
__global__ __launch_bounds__(128)
void gather_fuse(const int* __restrict__ T0, const int* __restrict__ T1,
                 const int* __restrict__ T2) {
    const int b = blockIdx.x;
    const int tid = threadIdx.x;
    const int lane = tid & 31;
    const int w = tid >> 5;

    __shared__ __align__(16) float sH[4 * 256];
    __shared__ __align__(16) float sQ[4 * 256];
    __shared__ int sT1[F1N];
    __shared__ int sT2[F1N * F2N];

    if (tid < F1N) sT1[tid] = T1[b * F1N + tid];
    for (int i = tid; i < F1N * F2N; i += 128) sT2[i] = T2[b * F1N * F2N + i];
    __syncthreads();

    const uint4* __restrict__ Pv = reinterpret_cast<const uint4*>(g_Ph);
    const uint4* __restrict__ Qv = reinterpret_cast<const uint4*>(g_Qh);

    float hacc[8], qacc[8];
#pragma unroll
    for (int c = 0; c < 8; c++) { hacc[c] = 0.f; qacc[c] = 0.f; }

    for (int i = w; i < F1N; i += 4) {
        const int n1 = sT1[i];
        uint4 pr = Pv[(size_t)n1 * 32 + lane];
        uint4 qr = Qv[(size_t)n1 * 32 + lane];

        uint4 a0 = Qv[(size_t)sT2[i * F2N + 0] * 32 + lane];
        __half2 s0 = ((const __half2*)&a0)[0];
        __half2 s1 = ((const __half2*)&a0)[1];
        __half2 s2 = ((const __half2*)&a0)[2];
        __half2 s3 = ((const __half2*)&a0)[3];
#pragma unroll
        for (int j = 1; j < F2N; j++) {
            uint4 aj = Qv[(size_t)sT2[i * F2N + j] * 32 + lane];
            s0 = __hadd2(s0, ((const __half2*)&aj)[0]);
            s1 = __hadd2(s1, ((const __half2*)&aj)[1]);
            s2 = __hadd2(s2, ((const __half2*)&aj)[2]);
            s3 = __hadd2(s3, ((const __half2*)&aj)[3]);
        }
        __half2 sv[4] = {s0, s1, s2, s3};
#pragma unroll
        for (int c = 0; c < 4; c++) {
            float2 sf = __half22float2(sv[c]);
            float2 pf = __half22float2(((const __half2*)&pr)[c]);
            float2 qf = __half22float2(((const __half2*)&qr)[c]);
            qacc[2 * c + 0] += qf.x;
            qacc[2 * c + 1] += qf.y;
            hacc[2 * c + 0] += fmaxf(fmaf(sf.x, 1.f / F2N, pf.x), 0.f);
            hacc[2 * c + 1] += fmaxf(fmaf(sf.y, 1.f / F2N, pf.y), 0.f);
        }
    }

    {
        float* ph = &sH[w * 256 + lane * 8];
        float* pq = &sQ[w * 256 + lane * 8];
        *reinterpret_cast<float4*>(ph)     = make_float4(hacc[0], hacc[1], hacc[2], hacc[3]);
        *reinterpret_cast<float4*>(ph + 4) = make_float4(hacc[4], hacc[5], hacc[6], hacc[7]);
        *reinterpret_cast<float4*>(pq)     = make_float4(qacc[0], qacc[1], qacc[2], qacc[3]);
        *reinterpret_cast<float4*>(pq + 4) = make_float4(qacc[4], qacc[5], qacc[6], qacc[7]);
    }
    __syncthreads();

    float hx = 0.f, hy = 0.f, qx = 0.f, qy = 0.f;
#pragma unroll
    for (int ww = 0; ww < 4; ww++) {
        float2 hv = *reinterpret_cast<const float2*>(&sH[ww * 256 + 2 * tid]);
        float2 qv = *reinterpret_cast<const float2*>(&sQ[ww * 256 + 2 * tid]);
        hx += hv.x; hy += hv.y;
        qx += qv.x; qy += qv.y;
    }
    float2 p0 = __half22float2(
        reinterpret_cast<const __half2*>(g_Ph)[(size_t)T0[b] * 128 + tid]);
    float h0x = fmaxf(fmaf(qx, 1.f / F1N, p0.x), 0.f);
    float h0y = fmaxf(fmaf(qy, 1.f / F1N, p0.y), 0.f);
    __half2* C2 = reinterpret_cast<__half2*>(g_combh);
    C2[(size_t)b * 256 + tid]       = __floats2half2_rn(h0x, h0y);
    C2[(size_t)b * 256 + 128 + tid] = __floats2half2_rn(hx * (1.f / F1N), hy * (1.f / F1N));
}

// ---------------- scores: 32 batch rows per block (unchanged) ----------------
__global__ __launch_bounds__(256)
void scores_k(float* __restrict__ out) {
    int b0 = blockIdx.x * 32;
    __shared__ __align__(16) float sE[32 * 257];
    int tid = threadIdx.x;
#pragma unroll
    for (int it = 0; it < 8; it++) {
        int i = tid + it * 256;
        int r = i >> 6, k4 = (i & 63) * 4;
        float4 v = *reinterpret_cast<const float4*>(&g_E[(size_t)(b0 + r) * 256 + k4]);
        float* p = &sE[r * 257 + k4];
        p[0] = v.x; p[1] = v.y; p[2] = v.z; p[3] = v.w;
    }
    __syncthreads();

    int col = tid & 63, rg = tid >> 6;
    float a[8];
#pragma unroll
    for (int i = 0; i < 8; i++) a[i] = 0.f;
#pragma unroll 4
    for (int k = 0; k < 256; k++) {
        float w = g_W3t[k * 64 + col];
        const float* pe = &sE[(rg * 8) * 257 + k];
#pragma unroll
        for (int i = 0; i < 8; i++) a[i] = fmaf(pe[i * 257], w, a[i]);
    }
#pragma unroll
    for (int i = 0; i < 8; i++)
        out[(size_t)(b0 + rg * 8 + i) * 64 + col] = a[i];
}

// ---------------- launch ----------------
extern "C" void kernel_launch(void* const* d_in, const int* in_sizes, int n_in,
                              void* d_out, int out_size) {
    const int*   T0  = (const int*)d_in[0];
    const int*   T1  = (const int*)d_in[1];
    const int*   T2  = (const int*)d_in[2];
    const float* emb = (const float*)d_in[3];
    const float* W1  = (const float*)d_in[4];
    const float* W2  = (const float*)d_in[5];
    const float* W3  = (const float*)d_in[6];
    float* out = (float*)d_out;
    (void)in_sizes; (void)n_in; (void)out_size;

    __half *embh, *Ph, *Qh, *B1h, *W2th, *combh;
    float* E;
    cudaGetSymbolAddress((void**)&embh,  g_embh);
    cudaGetSymbolAddress((void**)&Ph,    g_Ph);
    cudaGetSymbolAddress((void**)&Qh,    g_Qh);
    cudaGetSymbolAddress((void**)&B1h,   g_B1h);
    cudaGetSymbolAddress((void**)&W2th,  g_W2th);
    cudaGetSymbolAddress((void**)&combh, g_combh);
    cudaGetSymbolAddress((void**)&E,     g_E);

    cudaFuncSetAttribute((const void*)gemm_f16<false, 2, __half, true>,
                         cudaFuncAttributeMaxDynamicSharedMemorySize, SMEM_PQ);
    cudaFuncSetAttribute((const void*)gemm_f16<true, 1, float, false>,
                         cudaFuncAttributeMaxDynamicSharedMemorySize, SMEM_W2);

    // 1) conversions / weight prep
    conv_emb<<<NUM_NODES * 256 / 4 / 256, 256>>>(emb);
    prep_weights<<<512, 256>>>(W1, W2, W3);

    // 2) [P|Q] = embh @ B1h : [100000,256]x[256,512], split fp16 outputs
    {
        dim3 grid(4, (NUM_NODES + 127) / 128);
        gemm_f16<false, 2, __half, true><<<grid, 256, SMEM_PQ>>>(
            embh, B1h, Ph, Qh, NUM_NODES, 512, 256);
    }

    // 3) fused gathers/means/relu -> g_combh [4096, 512] fp16
    gather_fuse<<<BATCH, 128>>>(T0, T1, T2);

    // 4) E = relu(combh @ W2th): [4096,512]x[512,256] fp32 out, BM=64
    {
        dim3 grid(2, BATCH / 64);
        gemm_f16<true, 1, float, false><<<grid, 256, SMEM_W2>>>(
            combh, W2th, E, E, BATCH, 256, 512);
    }

    // 5) scores = E @ W3t (fp32 exact)
    scores_k<<<BATCH / 32, 256>>>(out);
}